// round 2
// baseline (speedup 1.0000x reference)
#include <cuda_runtime.h>
#include <cuda_bf16.h>
#include <math.h>

// Problem constants
#define BMAX 16384
#define KN   20       // neighbors
#define DD   128      // feature dim
#define TT   128      // time dim
#define EE   256      // embed dim
#define KDD  384      // key dim
#define NH   2        // heads

// ---------------- device scratch (static, allocation-free) ----------------
__device__ float g_feat[BMAX * DD];          // items_feat
__device__ float g_q[BMAX * EE];             // q projection
__device__ float g_r[BMAX * NH * KDD];       // per-head score vectors
__device__ float g_agg[BMAX * NH * KDD];     // attn-weighted kv aggregate
__device__ float g_attnout[BMAX * EE];       // after fused Wv@Wo
__device__ float g_h1[BMAX * DD];            // fc1 output
__device__ unsigned char g_invalid[BMAX];
__device__ float g_Wfused[NH * KDD * EE];    // Wv_h @ Wo_h fused
__device__ float g_WkT[NH * DD * KDD];       // Wk transposed per head
__device__ float g_cq[EE];                   // cos(time_b) @ Wq_bottom + bq
__device__ float g_bfused[EE];               // bv @ Wo + bo

// ---------------- prep kernels ----------------
__global__ void prep_cq(const float* __restrict__ Wq, const float* __restrict__ bq,
                        const float* __restrict__ time_b) {
    __shared__ float ctb[TT];
    int tid = threadIdx.x;
    if (tid < TT) ctb[tid] = cosf(time_b[tid]);
    __syncthreads();
    float acc = bq[tid];
    for (int t = 0; t < TT; t++) acc = fmaf(ctb[t], Wq[(DD + t) * EE + tid], acc);
    g_cq[tid] = acc;
}

__global__ void prep_bfused(const float* __restrict__ Wo, const float* __restrict__ bv,
                            const float* __restrict__ bo) {
    int tid = threadIdx.x;
    float acc = bo[tid];
    for (int e = 0; e < EE; e++) acc = fmaf(bv[e], Wo[e * EE + tid], acc);
    g_bfused[tid] = acc;
}

__global__ void prep_wkt(const float* __restrict__ Wk) {
    int idx = blockIdx.x * blockDim.x + threadIdx.x;
    if (idx >= NH * DD * KDD) return;
    int h = idx / (DD * KDD);
    int rem = idx - h * (DD * KDD);
    int e = rem / KDD;
    int j = rem - e * KDD;
    g_WkT[idx] = Wk[j * EE + h * DD + e];
}

__global__ void feat_kernel(const int* __restrict__ items_idxs,
                            const float* __restrict__ stat,
                            const float* __restrict__ mem, int B) {
    int idx = blockIdx.x * blockDim.x + threadIdx.x;
    if (idx >= B * DD) return;
    int b = idx >> 7, d = idx & 127;
    long it = items_idxs[b];
    g_feat[idx] = stat[it * DD + d] + mem[it * DD + d];
}

// ---------------- generic tiled fp32 GEMM ----------------
// C[M,N] = (A | A2 concat at ksplit)[M,Kd] @ B[Kd,N] (+colbias) (+relu) (zero rows where zrow)
__global__ void gemm_kernel(const float* __restrict__ A, int lda,
                            const float* __restrict__ A2, int lda2, int ksplit,
                            const float* __restrict__ Bm, int ldb,
                            float* __restrict__ C, int ldc,
                            int M, int N, int Kd,
                            const float* __restrict__ colbias,
                            const unsigned char* __restrict__ zrow,
                            int do_relu) {
    __shared__ float As[16][65];
    __shared__ float Bs[16][65];
    int tid = threadIdx.x;
    int tx = tid & 15, ty = tid >> 4;
    int row0 = blockIdx.y * 64, col0 = blockIdx.x * 64;
    float acc[4][4] = {};

    for (int k0 = 0; k0 < Kd; k0 += 16) {
        // A tile: 64 rows x 16 k, stored transposed As[k][row]
        #pragma unroll
        for (int l = 0; l < 4; l++) {
            int idx = tid + l * 256;
            int r = idx >> 4, c = idx & 15;
            int gr = row0 + r, gk = k0 + c;
            float v = 0.f;
            if (gr < M) {
                if (A2 && gk >= ksplit) v = A2[(long)gr * lda2 + (gk - ksplit)];
                else                    v = A[(long)gr * lda + gk];
            }
            As[c][r] = v;
        }
        // B tile: 16 k x 64 cols
        #pragma unroll
        for (int l = 0; l < 4; l++) {
            int idx = tid + l * 256;
            int r = idx >> 6, c = idx & 63;
            int gk = k0 + r, gc = col0 + c;
            Bs[r][c] = (gc < N) ? Bm[(long)gk * ldb + gc] : 0.f;
        }
        __syncthreads();
        #pragma unroll
        for (int kk = 0; kk < 16; kk++) {
            float a[4], bb[4];
            #pragma unroll
            for (int i = 0; i < 4; i++) a[i] = As[kk][ty + 16 * i];
            #pragma unroll
            for (int j = 0; j < 4; j++) bb[j] = Bs[kk][tx + 16 * j];
            #pragma unroll
            for (int i = 0; i < 4; i++)
                #pragma unroll
                for (int j = 0; j < 4; j++)
                    acc[i][j] = fmaf(a[i], bb[j], acc[i][j]);
        }
        __syncthreads();
    }
    #pragma unroll
    for (int i = 0; i < 4; i++) {
        int gr = row0 + ty + 16 * i;
        if (gr >= M) continue;
        bool z = (zrow != nullptr) && zrow[gr];
        #pragma unroll
        for (int j = 0; j < 4; j++) {
            int gc = col0 + tx + 16 * j;
            if (gc >= N) continue;
            float v = acc[i][j];
            if (colbias) v += colbias[gc];
            if (do_relu) v = fmaxf(v, 0.f);
            if (z) v = 0.f;
            C[(long)gr * ldc + gc] = v;
        }
    }
}

// ---------------- fused per-item attention ----------------
// builds kv rows once in SMEM, computes scores via r, softmax, and attn-weighted
// kv aggregate. 1 block per item, 128 threads.
__global__ void attn_kernel(const float* __restrict__ ts,
                            const int* __restrict__ inv_idx,
                            const int* __restrict__ vot_idx,
                            const int* __restrict__ edge_idx,
                            const float* __restrict__ edge_ts,
                            const float* __restrict__ users_mem,
                            const float* __restrict__ time_w,
                            const float* __restrict__ time_b,
                            const float* __restrict__ bk) {
    int b = blockIdx.x;
    int tid = threadIdx.x;
    int lane = tid & 31, warp = tid >> 5;

    __shared__ float kv_s[KN][KDD];
    __shared__ float r_s[NH * KDD];
    __shared__ float tw_s[TT], tb_s[TT];
    __shared__ float score_s[NH][KN];
    __shared__ float attn_s[NH][KN];
    __shared__ float sbias_s[NH];
    __shared__ int mask_s[KN];
    __shared__ int inv_s[KN], vot_s[KN];
    __shared__ float delta_s[KN];

    for (int i = tid; i < NH * KDD; i += 128) r_s[i] = g_r[(long)b * NH * KDD + i];
    if (tid < TT) { tw_s[tid] = time_w[tid]; tb_s[tid] = time_b[tid]; }
    if (tid < KN) {
        inv_s[tid] = inv_idx[b * KN + tid];
        vot_s[tid] = vot_idx[b * KN + tid];
        mask_s[tid] = (edge_idx[b * KN + tid] == 0);
        delta_s[tid] = ts[b] - edge_ts[b * KN + tid];
    }
    // bk . q per head (bk is zero in practice but honor it)
    if (warp < NH) {
        float s = 0.f;
        #pragma unroll
        for (int i = 0; i < 4; i++) {
            int e = lane + 32 * i;
            s = fmaf(bk[warp * DD + e], g_q[(long)b * EE + warp * DD + e], s);
        }
        for (int o = 16; o > 0; o >>= 1) s += __shfl_xor_sync(0xffffffff, s, o);
        if (lane == 0) sbias_s[warp] = s;
    }
    __syncthreads();
    if (tid == 0) {
        int inv = 1;
        for (int k = 0; k < KN; k++) inv &= mask_s[k];
        g_invalid[b] = (unsigned char)inv;
    }
    // build kv rows: [inviter(128) | voter(128) | cos(delta*w+b)(128)]
    for (int idx = tid; idx < KN * KDD; idx += 128) {
        int k = idx / KDD, j = idx - k * KDD;
        float v;
        if (j < DD)            v = users_mem[(long)inv_s[k] * DD + j];
        else if (j < 2 * DD)   v = users_mem[(long)vot_s[k] * DD + (j - DD)];
        else {
            int t = j - 2 * DD;
            v = cosf(fmaf(delta_s[k], tw_s[t], tb_s[t]));
        }
        kv_s[k][j] = v;
    }
    __syncthreads();
    // scores: 4 warps x 10 (h,k) pairs, dot-384 in smem
    #pragma unroll
    for (int i = 0; i < 10; i++) {
        int pair = warp * 10 + i;
        int h = pair / KN, k = pair - h * KN;
        const float* rp = &r_s[h * KDD];
        float s = 0.f;
        #pragma unroll
        for (int m = 0; m < KDD / 32; m++) {
            int jj = lane + 32 * m;
            s = fmaf(kv_s[k][jj], rp[jj], s);
        }
        for (int o = 16; o > 0; o >>= 1) s += __shfl_xor_sync(0xffffffff, s, o);
        if (lane == 0) {
            s = (s + sbias_s[h]) * 0.08838834764831845f; // 1/sqrt(128)
            if (mask_s[k]) s = -1e9f;
            score_s[h][k] = s;
        }
    }
    __syncthreads();
    // masked softmax per head (all-masked row -> uniform, zeroed downstream)
    if (warp < NH) {
        float s = (lane < KN) ? score_s[warp][lane] : -INFINITY;
        float mx = s;
        for (int o = 16; o > 0; o >>= 1) mx = fmaxf(mx, __shfl_xor_sync(0xffffffff, mx, o));
        float e = (lane < KN) ? expf(s - mx) : 0.f;
        float sum = e;
        for (int o = 16; o > 0; o >>= 1) sum += __shfl_xor_sync(0xffffffff, sum, o);
        if (lane < KN) attn_s[warp][lane] = e / sum;
    }
    __syncthreads();
    // aggregate: agg[h,j] = sum_k attn[h,k] * kv[k,j]
    for (int idx = tid; idx < NH * KDD; idx += 128) {
        int h = idx / KDD, jj = idx - h * KDD;
        float acc = 0.f;
        #pragma unroll
        for (int k = 0; k < KN; k++) acc = fmaf(attn_s[h][k], kv_s[k][jj], acc);
        g_agg[(long)b * NH * KDD + idx] = acc;
    }
}

// ---------------- host ----------------
static float* sym_addr(const void* sym) {
    void* p = nullptr;
    cudaGetSymbolAddress(&p, sym);
    return (float*)p;
}

extern "C" void kernel_launch(void* const* d_in, const int* in_sizes, int n_in,
                              void* d_out, int out_size) {
    const int*   items_idxs = (const int*)d_in[0];
    const float* timestamps = (const float*)d_in[1];
    const int*   inv_idx    = (const int*)d_in[2];
    const int*   vot_idx    = (const int*)d_in[3];
    const int*   edge_idx   = (const int*)d_in[4];
    const float* edge_ts    = (const float*)d_in[5];
    const float* stat       = (const float*)d_in[6];
    const float* imem       = (const float*)d_in[7];
    const float* umem       = (const float*)d_in[8];
    const float* time_w     = (const float*)d_in[9];
    const float* time_b     = (const float*)d_in[10];
    const float* Wq         = (const float*)d_in[11];
    const float* bq         = (const float*)d_in[12];
    const float* Wk         = (const float*)d_in[13];
    const float* bk         = (const float*)d_in[14];
    const float* Wv         = (const float*)d_in[15];
    const float* bv         = (const float*)d_in[16];
    const float* Wo         = (const float*)d_in[17];
    const float* bo         = (const float*)d_in[18];
    const float* fc1_w      = (const float*)d_in[19];
    const float* fc1_b      = (const float*)d_in[20];
    const float* fc2_w      = (const float*)d_in[21];
    const float* fc2_b      = (const float*)d_in[22];
    float* out = (float*)d_out;

    int B = in_sizes[0];

    float* p_feat    = sym_addr(g_feat);
    float* p_q       = sym_addr(g_q);
    float* p_r       = sym_addr(g_r);
    float* p_agg     = sym_addr(g_agg);
    float* p_attnout = sym_addr(g_attnout);
    float* p_h1      = sym_addr(g_h1);
    unsigned char* p_invalid = (unsigned char*)sym_addr(g_invalid);
    float* p_Wfused  = sym_addr(g_Wfused);
    float* p_WkT     = sym_addr(g_WkT);
    float* p_cq      = sym_addr(g_cq);
    float* p_bfused  = sym_addr(g_bfused);

    // --- prep (cheap, each call; deterministic) ---
    prep_cq<<<1, EE>>>(Wq, bq, time_b);
    prep_bfused<<<1, EE>>>(Wo, bv, bo);
    prep_wkt<<<(NH * DD * KDD + 255) / 256, 256>>>(Wk);
    // Wfused_h = Wv[:, h*128:(h+1)*128] @ Wo[h*128:(h+1)*128, :]
    for (int h = 0; h < NH; h++) {
        dim3 grid((EE + 63) / 64, (KDD + 63) / 64);
        gemm_kernel<<<grid, 256>>>(Wv + h * DD, EE, nullptr, 0, 0,
                                   Wo + (long)h * DD * EE, EE,
                                   p_Wfused + (long)h * KDD * EE, EE,
                                   KDD, EE, DD, nullptr, nullptr, 0);
    }

    // --- feat gather ---
    feat_kernel<<<(B * DD + 255) / 256, 256>>>(items_idxs, stat, imem, B);

    // --- q = feat @ Wq_top + cq ---
    {
        dim3 grid((EE + 63) / 64, (B + 63) / 64);
        gemm_kernel<<<grid, 256>>>(p_feat, DD, nullptr, 0, 0,
                                   Wq, EE, p_q, EE,
                                   B, EE, DD, p_cq, nullptr, 0);
    }
    // --- r_h = q_h @ WkT_h  ([B,128] @ [128,384]) ---
    for (int h = 0; h < NH; h++) {
        dim3 grid((KDD + 63) / 64, (B + 63) / 64);
        gemm_kernel<<<grid, 256>>>(p_q + h * DD, EE, nullptr, 0, 0,
                                   p_WkT + (long)h * DD * KDD, KDD,
                                   p_r + h * KDD, NH * KDD,
                                   B, KDD, DD, nullptr, nullptr, 0);
    }

    // --- fused attention (scores + softmax + aggregate) ---
    attn_kernel<<<B, 128>>>(timestamps, inv_idx, vot_idx, edge_idx, edge_ts,
                            umem, time_w, time_b, bk);

    // --- attnout = agg @ Wfused + bfused, zero invalid rows ---
    {
        dim3 grid((EE + 63) / 64, (B + 63) / 64);
        gemm_kernel<<<grid, 256>>>(p_agg, NH * KDD, nullptr, 0, 0,
                                   p_Wfused, EE, p_attnout, EE,
                                   B, EE, NH * KDD, p_bfused, p_invalid, 0);
    }
    // --- h1 = relu([attnout | feat] @ fc1_w + fc1_b) ---
    {
        dim3 grid((DD + 63) / 64, (B + 63) / 64);
        gemm_kernel<<<grid, 256>>>(p_attnout, EE, p_feat, DD, EE,
                                   fc1_w, DD, p_h1, DD,
                                   B, DD, EE + DD, fc1_b, nullptr, 1);
    }
    // --- out = h1 @ fc2_w + fc2_b ---
    {
        dim3 grid((DD + 63) / 64, (B + 63) / 64);
        gemm_kernel<<<grid, 256>>>(p_h1, DD, nullptr, 0, 0,
                                   fc2_w, DD, out, DD,
                                   B, DD, DD, fc2_b, nullptr, 0);
    }
}

// round 9
// speedup vs baseline: 2.0611x; 2.0611x over previous
#include <cuda_runtime.h>
#include <cuda_bf16.h>
#include <math.h>

// Problem constants
#define BMAX 16384
#define KN   20       // neighbors
#define DD   128      // feature dim
#define TT   128      // time dim
#define EE   256      // embed dim
#define KDD  384      // key dim
#define NH   2        // heads

// ---------------- device scratch (static, allocation-free) ----------------
__device__ __align__(256) float g_feat[BMAX * DD];
__device__ __align__(256) float g_q[BMAX * EE];
__device__ __align__(256) float g_r[BMAX * NH * KDD];
__device__ __align__(256) float g_agg[BMAX * NH * KDD];
__device__ __align__(256) float g_attnout[BMAX * EE];
__device__ __align__(256) float g_h1[BMAX * DD];
__device__ unsigned char g_invalid[BMAX];
__device__ __align__(256) float g_Wfused[NH * KDD * EE];
__device__ __align__(256) float g_WkT[NH * DD * KDD];
__device__ __align__(256) float g_cq[EE];
__device__ __align__(256) float g_bfused[EE];

// ---------------- prep kernels ----------------
__global__ void prep_cq(const float* __restrict__ Wq, const float* __restrict__ bq,
                        const float* __restrict__ time_b) {
    __shared__ float ctb[TT];
    int tid = threadIdx.x;
    if (tid < TT) ctb[tid] = cosf(time_b[tid]);
    __syncthreads();
    float acc = bq[tid];
    for (int t = 0; t < TT; t++) acc = fmaf(ctb[t], Wq[(DD + t) * EE + tid], acc);
    g_cq[tid] = acc;
}

__global__ void prep_bfused(const float* __restrict__ Wo, const float* __restrict__ bv,
                            const float* __restrict__ bo) {
    int tid = threadIdx.x;
    float acc = bo[tid];
    for (int e = 0; e < EE; e++) acc = fmaf(bv[e], Wo[e * EE + tid], acc);
    g_bfused[tid] = acc;
}

__global__ void prep_wkt(const float* __restrict__ Wk) {
    int idx = blockIdx.x * blockDim.x + threadIdx.x;
    if (idx >= NH * DD * KDD) return;
    int h = idx / (DD * KDD);
    int rem = idx - h * (DD * KDD);
    int e = rem / KDD;
    int j = rem - e * KDD;
    g_WkT[idx] = Wk[j * EE + h * DD + e];
}

__global__ void feat_kernel(const int* __restrict__ items_idxs,
                            const float* __restrict__ stat,
                            const float* __restrict__ mem, int B) {
    int idx = blockIdx.x * blockDim.x + threadIdx.x;
    if (idx >= B * DD / 4) return;
    int b = idx >> 5, d4 = idx & 31;
    long it = items_idxs[b];
    float4 a = ((const float4*)stat)[it * 32 + d4];
    float4 m = ((const float4*)mem)[it * 32 + d4];
    a.x += m.x; a.y += m.y; a.z += m.z; a.w += m.w;
    ((float4*)g_feat)[idx] = a;
}

// ---------------- tiled fp32 GEMM: 128x64 tile, 8x4/thread, double-buffered ----------------
// Requires: M%128==0, N%64==0, Kd%16==0, all pointers & leading dims 16B-aligned,
// ksplit%16==0. Batched over blockIdx.z via element strides sA/sB/sC.
#define BM 128
#define BN 64
#define BKG 16

__global__ __launch_bounds__(256) void gemm2(
        const float* __restrict__ A, int lda, long sA,
        const float* __restrict__ A2, int lda2, int ksplit,
        const float* __restrict__ Bm, int ldb, long sB,
        float* __restrict__ C, int ldc, long sC,
        int M, int N, int Kd,
        const float* __restrict__ colbias,
        const unsigned char* __restrict__ zrow,
        int do_relu) {
    __shared__ __align__(16) float As[2][BKG][BM + 4];
    __shared__ __align__(16) float Bs[2][BKG][BN];

    int z = blockIdx.z;
    A += (long)z * sA;
    Bm += (long)z * sB;
    C += (long)z * sC;

    int tid = threadIdx.x;
    int tx = tid & 15;        // N dir: 16 x 4 = 64
    int ty = tid >> 4;        // M dir: 16 x 8 = 128
    int row0 = blockIdx.y * BM, col0 = blockIdx.x * BN;

    float acc[8][4];
    #pragma unroll
    for (int i = 0; i < 8; i++)
        #pragma unroll
        for (int j = 0; j < 4; j++) acc[i][j] = 0.f;

    int nk = Kd / BKG;

    float4 pa[2], pb;

    auto loadA = [&](int k0, float4* dst) {
        #pragma unroll
        for (int l = 0; l < 2; l++) {
            int i = l * 256 + tid;
            int r = i >> 2, c = (i & 3) * 4;
            int gr = row0 + r, gk = k0 + c;
            const float* src;
            if (A2 && gk >= ksplit) src = A2 + (long)gr * lda2 + (gk - ksplit);
            else                    src = A  + (long)gr * lda  + gk;
            dst[l] = *(const float4*)src;
        }
    };
    auto loadB = [&](int k0, float4* dst) {
        int r = tid >> 4, c = (tid & 15) * 4;
        *dst = *(const float4*)(Bm + (long)(k0 + r) * ldb + col0 + c);
    };
    auto storeA = [&](int buf, const float4* v) {
        #pragma unroll
        for (int l = 0; l < 2; l++) {
            int i = l * 256 + tid;
            int r = i >> 2, c = (i & 3) * 4;
            As[buf][c + 0][r] = v[l].x;
            As[buf][c + 1][r] = v[l].y;
            As[buf][c + 2][r] = v[l].z;
            As[buf][c + 3][r] = v[l].w;
        }
    };
    auto storeB = [&](int buf, float4 v) {
        int r = tid >> 4, c = (tid & 15) * 4;
        *(float4*)&Bs[buf][r][c] = v;
    };

    loadA(0, pa);
    loadB(0, &pb);
    storeA(0, pa);
    storeB(0, pb);
    __syncthreads();

    int buf = 0;
    for (int kt = 0; kt < nk; kt++) {
        if (kt + 1 < nk) {
            loadA((kt + 1) * BKG, pa);
            loadB((kt + 1) * BKG, &pb);
        }
        #pragma unroll
        for (int kk = 0; kk < BKG; kk++) {
            float4 a0 = *(const float4*)&As[buf][kk][ty * 8];
            float4 a1 = *(const float4*)&As[buf][kk][ty * 8 + 4];
            float4 b  = *(const float4*)&Bs[buf][kk][tx * 4];
            float av[8] = {a0.x, a0.y, a0.z, a0.w, a1.x, a1.y, a1.z, a1.w};
            float bv[4] = {b.x, b.y, b.z, b.w};
            #pragma unroll
            for (int i = 0; i < 8; i++)
                #pragma unroll
                for (int j = 0; j < 4; j++)
                    acc[i][j] = fmaf(av[i], bv[j], acc[i][j]);
        }
        if (kt + 1 < nk) {
            storeA(buf ^ 1, pa);
            storeB(buf ^ 1, pb);
        }
        __syncthreads();
        buf ^= 1;
    }

    int gc = col0 + tx * 4;
    float4 bias = make_float4(0.f, 0.f, 0.f, 0.f);
    if (colbias) bias = *(const float4*)(colbias + gc);
    #pragma unroll
    for (int i = 0; i < 8; i++) {
        int gr = row0 + ty * 8 + i;
        float4 v = make_float4(acc[i][0] + bias.x, acc[i][1] + bias.y,
                               acc[i][2] + bias.z, acc[i][3] + bias.w);
        if (do_relu) {
            v.x = fmaxf(v.x, 0.f); v.y = fmaxf(v.y, 0.f);
            v.z = fmaxf(v.z, 0.f); v.w = fmaxf(v.w, 0.f);
        }
        if (zrow && zrow[gr]) v = make_float4(0.f, 0.f, 0.f, 0.f);
        *(float4*)(C + (long)gr * ldc + gc) = v;
    }
}

// ---------------- fused per-item attention (vectorized) ----------------
__global__ void attn_kernel(const float* __restrict__ ts,
                            const int* __restrict__ inv_idx,
                            const int* __restrict__ vot_idx,
                            const int* __restrict__ edge_idx,
                            const float* __restrict__ edge_ts,
                            const float* __restrict__ users_mem,
                            const float* __restrict__ time_w,
                            const float* __restrict__ time_b,
                            const float* __restrict__ bk) {
    int b = blockIdx.x;
    int tid = threadIdx.x;
    int lane = tid & 31, warp = tid >> 5;

    __shared__ __align__(16) float kv_s[KN][KDD];
    __shared__ __align__(16) float r_s[NH * KDD];
    __shared__ __align__(16) float tw_s[TT], tb_s[TT];
    __shared__ float score_s[NH][KN];
    __shared__ float attn_s[NH][KN];
    __shared__ float sbias_s[NH];
    __shared__ int mask_s[KN];
    __shared__ int inv_s[KN], vot_s[KN];
    __shared__ float delta_s[KN];

    // r (768 floats = 192 float4)
    {
        const float4* src = (const float4*)(g_r + (long)b * NH * KDD);
        float4* dst = (float4*)r_s;
        for (int i = tid; i < NH * KDD / 4; i += 128) dst[i] = src[i];
    }
    if (tid < TT) { tw_s[tid] = time_w[tid]; tb_s[tid] = time_b[tid]; }
    if (tid < KN) {
        inv_s[tid] = inv_idx[b * KN + tid];
        vot_s[tid] = vot_idx[b * KN + tid];
        mask_s[tid] = (edge_idx[b * KN + tid] == 0);
        delta_s[tid] = ts[b] - edge_ts[b * KN + tid];
    }
    // bk . q per head
    if (warp < NH) {
        float s = 0.f;
        #pragma unroll
        for (int i = 0; i < 4; i++) {
            int e = lane + 32 * i;
            s = fmaf(bk[warp * DD + e], g_q[(long)b * EE + warp * DD + e], s);
        }
        for (int o = 16; o > 0; o >>= 1) s += __shfl_xor_sync(0xffffffff, s, o);
        if (lane == 0) sbias_s[warp] = s;
    }
    __syncthreads();
    if (tid == 0) {
        int inv = 1;
        for (int k = 0; k < KN; k++) inv &= mask_s[k];
        g_invalid[b] = (unsigned char)inv;
    }
    // build kv rows: [inviter(128) | voter(128) | cos(delta*w+b)(128)]
    for (int s = tid; s < KN * (KDD / 4); s += 128) {
        int k = s / 96, j4 = s - k * 96;
        float4 v;
        if (j4 < 32) {
            v = ((const float4*)users_mem)[(long)inv_s[k] * 32 + j4];
        } else if (j4 < 64) {
            v = ((const float4*)users_mem)[(long)vot_s[k] * 32 + (j4 - 32)];
        } else {
            int t = (j4 - 64) * 4;
            float d = delta_s[k];
            v.x = cosf(fmaf(d, tw_s[t + 0], tb_s[t + 0]));
            v.y = cosf(fmaf(d, tw_s[t + 1], tb_s[t + 1]));
            v.z = cosf(fmaf(d, tw_s[t + 2], tb_s[t + 2]));
            v.w = cosf(fmaf(d, tw_s[t + 3], tb_s[t + 3]));
        }
        *(float4*)&kv_s[k][j4 * 4] = v;
    }
    __syncthreads();
    // scores: 4 warps x 10 (h,k) pairs, float4 dot-384
    #pragma unroll
    for (int i = 0; i < 10; i++) {
        int pair = warp * 10 + i;
        int h = pair / KN, k = pair - h * KN;
        const float4* rp = (const float4*)&r_s[h * KDD];
        const float4* kp = (const float4*)&kv_s[k][0];
        float s = 0.f;
        #pragma unroll
        for (int m = 0; m < 3; m++) {
            int jj = lane + 32 * m;
            float4 a = kp[jj], c = rp[jj];
            s = fmaf(a.x, c.x, s); s = fmaf(a.y, c.y, s);
            s = fmaf(a.z, c.z, s); s = fmaf(a.w, c.w, s);
        }
        for (int o = 16; o > 0; o >>= 1) s += __shfl_xor_sync(0xffffffff, s, o);
        if (lane == 0) {
            s = (s + sbias_s[h]) * 0.08838834764831845f; // 1/sqrt(128)
            if (mask_s[k]) s = -1e9f;
            score_s[h][k] = s;
        }
    }
    __syncthreads();
    // masked softmax per head
    if (warp < NH) {
        float s = (lane < KN) ? score_s[warp][lane] : -INFINITY;
        float mx = s;
        for (int o = 16; o > 0; o >>= 1) mx = fmaxf(mx, __shfl_xor_sync(0xffffffff, mx, o));
        float e = (lane < KN) ? expf(s - mx) : 0.f;
        float sum = e;
        for (int o = 16; o > 0; o >>= 1) sum += __shfl_xor_sync(0xffffffff, sum, o);
        if (lane < KN) attn_s[warp][lane] = e / sum;
    }
    __syncthreads();
    // aggregate: agg[h,j4] = sum_k attn[h,k] * kv[k,j4]
    for (int s = tid; s < NH * (KDD / 4); s += 128) {
        int h = s / 96, j4 = s - h * 96;
        float4 acc = make_float4(0.f, 0.f, 0.f, 0.f);
        #pragma unroll
        for (int k = 0; k < KN; k++) {
            float w = attn_s[h][k];
            float4 v = *(const float4*)&kv_s[k][j4 * 4];
            acc.x = fmaf(w, v.x, acc.x); acc.y = fmaf(w, v.y, acc.y);
            acc.z = fmaf(w, v.z, acc.z); acc.w = fmaf(w, v.w, acc.w);
        }
        ((float4*)(g_agg + (long)b * NH * KDD))[s] = acc;
    }
}

// ---------------- host ----------------
static float* sym_addr(const void* sym) {
    void* p = nullptr;
    cudaGetSymbolAddress(&p, sym);
    return (float*)p;
}

extern "C" void kernel_launch(void* const* d_in, const int* in_sizes, int n_in,
                              void* d_out, int out_size) {
    const int*   items_idxs = (const int*)d_in[0];
    const float* timestamps = (const float*)d_in[1];
    const int*   inv_idx    = (const int*)d_in[2];
    const int*   vot_idx    = (const int*)d_in[3];
    const int*   edge_idx   = (const int*)d_in[4];
    const float* edge_ts    = (const float*)d_in[5];
    const float* stat       = (const float*)d_in[6];
    const float* imem       = (const float*)d_in[7];
    const float* umem       = (const float*)d_in[8];
    const float* time_w     = (const float*)d_in[9];
    const float* time_b     = (const float*)d_in[10];
    const float* Wq         = (const float*)d_in[11];
    const float* bq         = (const float*)d_in[12];
    const float* Wk         = (const float*)d_in[13];
    const float* bk         = (const float*)d_in[14];
    const float* Wv         = (const float*)d_in[15];
    const float* bv         = (const float*)d_in[16];
    const float* Wo         = (const float*)d_in[17];
    const float* bo         = (const float*)d_in[18];
    const float* fc1_w      = (const float*)d_in[19];
    const float* fc1_b      = (const float*)d_in[20];
    const float* fc2_w      = (const float*)d_in[21];
    const float* fc2_b      = (const float*)d_in[22];
    float* out = (float*)d_out;

    int B = in_sizes[0];

    float* p_feat    = sym_addr(g_feat);
    float* p_q       = sym_addr(g_q);
    float* p_r       = sym_addr(g_r);
    float* p_agg     = sym_addr(g_agg);
    float* p_attnout = sym_addr(g_attnout);
    float* p_h1      = sym_addr(g_h1);
    unsigned char* p_invalid = (unsigned char*)sym_addr(g_invalid);
    float* p_Wfused  = sym_addr(g_Wfused);
    float* p_WkT     = sym_addr(g_WkT);
    float* p_cq      = sym_addr(g_cq);
    float* p_bfused  = sym_addr(g_bfused);

    // --- prep ---
    prep_cq<<<1, EE>>>(Wq, bq, time_b);
    prep_bfused<<<1, EE>>>(Wo, bv, bo);
    prep_wkt<<<(NH * DD * KDD + 255) / 256, 256>>>(Wk);
    // Wfused_h = Wv[:, h*128:(h+1)*128] @ Wo[h*128:(h+1)*128, :]  (batched over h)
    {
        dim3 grid(EE / BN, KDD / BM, NH);
        gemm2<<<grid, 256>>>(Wv, EE, DD,
                             nullptr, 0, 0,
                             Wo, EE, (long)DD * EE,
                             p_Wfused, EE, (long)KDD * EE,
                             KDD, EE, DD, nullptr, nullptr, 0);
    }

    // --- feat gather ---
    feat_kernel<<<(B * DD / 4 + 255) / 256, 256>>>(items_idxs, stat, imem, B);

    // --- q = feat @ Wq_top + cq ---
    {
        dim3 grid(EE / BN, B / BM, 1);
        gemm2<<<grid, 256>>>(p_feat, DD, 0, nullptr, 0, 0,
                             Wq, EE, 0,
                             p_q, EE, 0,
                             B, EE, DD, p_cq, nullptr, 0);
    }
    // --- r_h = q_h @ WkT_h  (batched over h) ---
    {
        dim3 grid(KDD / BN, B / BM, NH);
        gemm2<<<grid, 256>>>(p_q, EE, DD,
                             nullptr, 0, 0,
                             p_WkT, KDD, (long)DD * KDD,
                             p_r, NH * KDD, KDD,
                             B, KDD, DD, nullptr, nullptr, 0);
    }

    // --- fused attention ---
    attn_kernel<<<B, 128>>>(timestamps, inv_idx, vot_idx, edge_idx, edge_ts,
                            umem, time_w, time_b, bk);

    // --- attnout = agg @ Wfused + bfused, zero invalid rows ---
    {
        dim3 grid(EE / BN, B / BM, 1);
        gemm2<<<grid, 256>>>(p_agg, NH * KDD, 0, nullptr, 0, 0,
                             p_Wfused, EE, 0,
                             p_attnout, EE, 0,
                             B, EE, NH * KDD, p_bfused, p_invalid, 0);
    }
    // --- h1 = relu([attnout | feat] @ fc1_w + fc1_b) ---
    {
        dim3 grid(DD / BN, B / BM, 1);
        gemm2<<<grid, 256>>>(p_attnout, EE, 0, p_feat, DD, EE,
                             fc1_w, DD, 0,
                             p_h1, DD, 0,
                             B, DD, EE + DD, fc1_b, nullptr, 1);
    }
    // --- out = h1 @ fc2_w + fc2_b ---
    {
        dim3 grid(DD / BN, B / BM, 1);
        gemm2<<<grid, 256>>>(p_h1, DD, 0, nullptr, 0, 0,
                             fc2_w, DD, 0,
                             out, DD, 0,
                             B, DD, DD, fc2_b, nullptr, 0);
    }
}